// round 6
// baseline (speedup 1.0000x reference)
#include <cuda_runtime.h>
#include <cuda_bf16.h>
#include <mma.h>
#include <math.h>

using namespace nvcuda;

// ---------------- problem constants ----------------
#define BB 2
#define LL 2048
#define NC 3
#define DMC 256
#define DM 768          // DMC*NC
#define DI 1536         // 2*DM
#define DS 16
#define DR 48
#define DCV 4
#define NLAY 4
#define DXP 80          // DR + 2*DS
#define NROWS (BB*LL)   // 4096
#define NCHK 32
#define CLEN 64         // LL / NCHK

// ---------------- scratch (device globals; no allocs) ----------------
__device__ float g_H[NROWS*DM];
__device__ float g_XN[NROWS*DM];
__device__ float g_XZ[NROWS*2*DI];
__device__ float g_U[NROWS*DI];
__device__ float g_DBC[NROWS*DXP];
__device__ float g_DELTA[NROWS*DI];
__device__ float g_Y[NROWS*DI];
__device__ float g_CP[BB*DI*NCHK*DS];   // chunk decay products
__device__ float g_CH[BB*DI*NCHK*DS];   // chunk end-states -> start-states

// ---------------- cp.async helpers ----------------
__device__ __forceinline__ void cp16(void* smem, const void* gmem, bool pred) {
    unsigned s = (unsigned)__cvta_generic_to_shared(smem);
    int sz = pred ? 16 : 0;
    asm volatile("cp.async.cg.shared.global [%0], [%1], 16, %2;\n"
                 :: "r"(s), "l"(gmem), "r"(sz));
}
__device__ __forceinline__ void cp_commit() { asm volatile("cp.async.commit_group;\n"); }
template<int N> __device__ __forceinline__ void cp_wait() {
    asm volatile("cp.async.wait_group %0;\n" :: "n"(N));
}

// ---------------- embedding gather ----------------
__global__ void embed_kernel(const int* __restrict__ tokens,
                             const float* __restrict__ emb) {
    int i = blockIdx.x * blockDim.x + threadIdx.x;
    if (i >= NROWS*DM) return;
    int row = i / DM;
    int col = i % DM;
    int c = col / DMC, j = col % DMC;
    int tok = tokens[row*NC + c];
    g_H[i] = emb[tok*DMC + j];
}

// ---------------- rmsnorm ----------------
__global__ void rmsnorm_kernel(const float* __restrict__ in,
                               const float* __restrict__ w,
                               float* __restrict__ out) {
    int row = blockIdx.x;
    const float* x = in + (size_t)row*DM;
    float s = 0.f;
    for (int i = threadIdx.x; i < DM; i += 256) { float v = x[i]; s += v*v; }
    __shared__ float red[256];
    red[threadIdx.x] = s;
    __syncthreads();
    for (int o = 128; o; o >>= 1) {
        if (threadIdx.x < o) red[threadIdx.x] += red[threadIdx.x + o];
        __syncthreads();
    }
    float scale = rsqrtf(red[0] / (float)DM + 1e-5f);
    for (int i = threadIdx.x; i < DM; i += 256)
        out[(size_t)row*DM + i] = x[i] * scale * w[i];
}

// ---------------- zero fill ----------------
__global__ void zero_kernel(float* __restrict__ p, int n) {
    int i = blockIdx.x * blockDim.x + threadIdx.x;
    if (i < n) p[i] = 0.f;
}

// ============================================================
// TF32 tensor-core GEMM, cp.async double-buffered, fp32 operands.
// C[M,N] = A[M,K] * W[N,K]^T. Block 128x128, K-tile 32, 8 warps (4m x 2n).
// EPI: 0 = store fp32, 2 = softplus(acc+bias[n]), 3 = atomicAdd
// ============================================================
#define TM 128
#define TN 128
#define TK 32
#define TLD 40                       // padded smem leading dim (floats)
#define BUFE (TM*TLD)                // floats per (matrix, stage)
#define GEMM_SMEM (4*BUFE*sizeof(float))   // 2 matrices * 2 stages = 81920 B

template<typename F>
__device__ __forceinline__ void to_tf32(F& f) {
    #pragma unroll
    for (int i = 0; i < f.num_elements; i++)
        f.x[i] = wmma::__float_to_tf32(f.x[i]);
}

template<int EPI>
__global__ __launch_bounds__(256)
void mmgemm(const float* __restrict__ A, const float* __restrict__ W,
            float* __restrict__ C, const float* __restrict__ bias,
            int N, int Kmax, int lda, int ldw, int kchunk) {
    extern __shared__ float smem[];
    float* sA = smem;                 // [2][BUFE]
    float* sB = smem + 2*BUFE;        // [2][BUFE]

    int m0 = blockIdx.y * TM;
    int n0 = blockIdx.x * TN;
    int kb = blockIdx.z * kchunk;
    int ke = kb + kchunk;

    int tid  = threadIdx.x;
    int row  = tid >> 1;              // 0..127
    int koff = (tid & 1) * 16;        // 0 or 16 (floats)
    int warp = tid >> 5;
    int lid  = tid & 31;
    int wm = warp & 3;                // m offset wm*32
    int wn = warp >> 2;               // n offset wn*64

    wmma::fragment<wmma::accumulator, 16, 16, 8, float> acc[2][4];
    #pragma unroll
    for (int i = 0; i < 2; i++)
        #pragma unroll
        for (int j = 0; j < 4; j++)
            wmma::fill_fragment(acc[i][j], 0.f);

    bool wrow_ok = (n0 + row) < N;
    const float* apF = A + (size_t)(m0 + row) * lda;
    const float* wpF = W + (size_t)(wrow_ok ? (n0 + row) : 0) * ldw;

    auto load_stage = [&](int buf, int kt) {
        #pragma unroll
        for (int h = 0; h < 4; h++) {
            int kc = kt + koff + h*4;
            bool kok = kc < Kmax;
            int so = buf*BUFE + row*TLD + koff + h*4;
            cp16(sA + so, apF + kc, kok);
            cp16(sB + so, wpF + kc, kok && wrow_ok);
        }
    };

    load_stage(0, kb);
    cp_commit();

    int buf = 0;
    for (int kt = kb; kt < ke; kt += TK) {
        bool hn = (kt + TK) < ke;
        if (hn) { load_stage(buf ^ 1, kt + TK); cp_commit(); }
        if (hn) cp_wait<1>(); else cp_wait<0>();
        __syncthreads();

        int bo = buf*BUFE;
        #pragma unroll
        for (int ks = 0; ks < TK; ks += 8) {
            wmma::fragment<wmma::matrix_a, 16, 16, 8, wmma::precision::tf32, wmma::row_major> fa[2];
            wmma::fragment<wmma::matrix_b, 16, 16, 8, wmma::precision::tf32, wmma::col_major> fb[4];
            #pragma unroll
            for (int i = 0; i < 2; i++) {
                wmma::load_matrix_sync(fa[i], sA + bo + (wm*32 + 16*i)*TLD + ks, TLD);
                to_tf32(fa[i]);
            }
            #pragma unroll
            for (int j = 0; j < 4; j++) {
                wmma::load_matrix_sync(fb[j], sB + bo + (wn*64 + 16*j)*TLD + ks, TLD);
                to_tf32(fb[j]);
            }
            #pragma unroll
            for (int i = 0; i < 2; i++)
                #pragma unroll
                for (int j = 0; j < 4; j++)
                    wmma::mma_sync(acc[i][j], fa[i], fb[j], acc[i][j]);
        }
        __syncthreads();
        buf ^= 1;
    }

    if (EPI == 0) {
        #pragma unroll
        for (int i = 0; i < 2; i++)
            #pragma unroll
            for (int j = 0; j < 4; j++)
                wmma::store_matrix_sync(C + (size_t)(m0 + wm*32 + 16*i)*N + n0 + wn*64 + 16*j,
                                        acc[i][j], N, wmma::mem_row_major);
    } else {
        float* scratch = smem + warp * 320;
        #pragma unroll
        for (int i = 0; i < 2; i++)
            #pragma unroll
            for (int j = 0; j < 4; j++) {
                __syncwarp();
                wmma::store_matrix_sync(scratch, acc[i][j], 20, wmma::mem_row_major);
                __syncwarp();
                #pragma unroll
                for (int e = 0; e < 8; e++) {
                    int idx = lid*8 + e;
                    int r = idx >> 4, c = idx & 15;
                    int n = n0 + wn*64 + 16*j + c;
                    if (n < N) {
                        int m = m0 + wm*32 + 16*i + r;
                        size_t o = (size_t)m*N + n;
                        float v = scratch[r*20 + c];
                        if (EPI == 2) {
                            float t = v + bias[n];
                            C[o] = (t > 20.f) ? t : log1pf(expf(t));
                        } else {
                            atomicAdd(&C[o], v);
                        }
                    }
                }
            }
    }
}

// ---------------- depthwise causal conv + bias + silu ----------------
__global__ void conv_silu_kernel(const float* __restrict__ cw,
                                 const float* __restrict__ cb) {
    int i = blockIdx.x * blockDim.x + threadIdx.x;
    if (i >= NROWS*DI) return;
    int d = i % DI;
    int row = i / DI;
    int t = row % LL, b = row / LL;
    float w0 = cw[d*DCV + 0], w1 = cw[d*DCV + 1], w2 = cw[d*DCV + 2], w3 = cw[d*DCV + 3];
    float acc = cb[d];
    const float* base = g_XZ + (size_t)(b*LL)*(2*DI) + d;
    if (t >= 3) acc += base[(size_t)(t-3)*(2*DI)] * w0;
    if (t >= 2) acc += base[(size_t)(t-2)*(2*DI)] * w1;
    if (t >= 1) acc += base[(size_t)(t-1)*(2*DI)] * w2;
    acc += base[(size_t)t*(2*DI)] * w3;
    g_U[i] = acc / (1.f + expf(-acc));
}

// ============================================================
// Chunked selective scan (3 phases).
// ============================================================
__global__ void scanA_kernel(const float* __restrict__ A_log_l) {
    int tid = threadIdx.x;
    int s = tid & 15;
    int gi = blockIdx.x * 16 + (tid >> 4);
    int ch = gi % (BB*DI);
    int c  = gi / (BB*DI);
    int b = ch / DI, d = ch % DI;

    float A = -expf(A_log_l[d*DS + s]);
    const float* delta_p = g_DELTA + ((size_t)(b*LL) + c*CLEN)*DI + d;
    const float* u_p     = g_U     + ((size_t)(b*LL) + c*CLEN)*DI + d;
    const float* dbc_p   = g_DBC   + ((size_t)(b*LL) + c*CLEN)*DXP;

    float h = 0.f, P = 1.f;
    for (int t = 0; t < CLEN; t++) {
        float dt = delta_p[(size_t)t*DI];
        float ut = u_p[(size_t)t*DI];
        float Bs = dbc_p[(size_t)t*DXP + DR + s];
        float dA = __expf(dt * A);
        h = dA * h + (dt * ut) * Bs;
        P *= dA;
    }
    size_t idx = ((size_t)ch*NCHK + c)*DS + s;
    g_CH[idx] = h;
    g_CP[idx] = P;
}

__global__ void scanB_kernel() {
    int i = blockIdx.x * blockDim.x + threadIdx.x;   // i = ch*DS + s
    if (i >= BB*DI*DS) return;
    int ch = i >> 4, s = i & 15;
    size_t base = (size_t)ch*NCHK*DS + s;
    float h0 = 0.f;
    for (int c = 0; c < NCHK; c++) {
        float he = g_CH[base + (size_t)c*DS];
        float P  = g_CP[base + (size_t)c*DS];
        g_CH[base + (size_t)c*DS] = h0;   // start-state for chunk c
        h0 = P * h0 + he;
    }
}

__global__ void scanC_kernel(const float* __restrict__ A_log_l,
                             const float* __restrict__ D_l) {
    int tid = threadIdx.x;
    int s = tid & 15;
    int gi = blockIdx.x * 16 + (tid >> 4);
    int ch = gi % (BB*DI);
    int c  = gi / (BB*DI);
    int b = ch / DI, d = ch % DI;

    float A = -expf(A_log_l[d*DS + s]);
    float Dd = D_l[d];
    float h = g_CH[((size_t)ch*NCHK + c)*DS + s];

    const float* delta_p = g_DELTA + ((size_t)(b*LL) + c*CLEN)*DI + d;
    const float* u_p     = g_U     + ((size_t)(b*LL) + c*CLEN)*DI + d;
    const float* z_p     = g_XZ    + ((size_t)(b*LL) + c*CLEN)*(2*DI) + DI + d;
    const float* dbc_p   = g_DBC   + ((size_t)(b*LL) + c*CLEN)*DXP;
    size_t ybase         = ((size_t)(b*LL) + c*CLEN)*DI + d;

    for (int t = 0; t < CLEN; t++) {
        float dt = delta_p[(size_t)t*DI];
        float ut = u_p[(size_t)t*DI];
        float Bs = dbc_p[(size_t)t*DXP + DR + s];
        float Cs = dbc_p[(size_t)t*DXP + DR + DS + s];
        float dA = __expf(dt * A);
        h = dA * h + (dt * ut) * Bs;
        float yv = h * Cs;
        yv += __shfl_down_sync(0xffffffffu, yv, 8, 16);
        yv += __shfl_down_sync(0xffffffffu, yv, 4, 16);
        yv += __shfl_down_sync(0xffffffffu, yv, 2, 16);
        yv += __shfl_down_sync(0xffffffffu, yv, 1, 16);
        if (s == 0) {
            float z = z_p[(size_t)t*(2*DI)];
            float silu_z = z / (1.f + __expf(-z));
            g_Y[ybase + (size_t)t*DI] = (yv + ut * Dd) * silu_z;
        }
    }
}

// ---------------- heads ----------------
__global__ void topic_kernel(const float* __restrict__ xfin,
                             const float* __restrict__ tw,
                             const float* __restrict__ tb,
                             float* __restrict__ out) {
    int w = threadIdx.x >> 5, lane = threadIdx.x & 31;
    if (w >= BB*3) return;
    int b = w / 3, c = w % 3;
    const float* p  = xfin + (size_t)(b*LL)*DM;
    const float* wt = tw + (size_t)c*DM;
    float s = 0.f;
    for (int i = lane; i < DM; i += 32) s += p[i] * wt[i];
    for (int o = 16; o; o >>= 1) s += __shfl_down_sync(0xffffffffu, s, o);
    if (lane == 0) out[b*3 + c] = s + tb[c];
}

__global__ void loss_kernel(float* __restrict__ out, const int* __restrict__ labels) {
    if (threadIdx.x != 0 || blockIdx.x != 0) return;
    float sum = 0.f, cnt = 0.f;
    for (int b = 0; b < BB; b++) {
        float t0 = out[b*3+0], t1 = out[b*3+1], t2 = out[b*3+2];
        float m = fmaxf(t0, fmaxf(t1, t2));
        float lse = m + logf(expf(t0-m) + expf(t1-m) + expf(t2-m));
        int lab = labels[b];
        float nll = lse - out[b*3 + lab];
        if (lab != 0) { sum += nll; cnt += 1.f; }
    }
    out[6] = sum / fmaxf(cnt, 1.f);
}

// ---------------- driver ----------------
extern "C" void kernel_launch(void* const* d_in, const int* in_sizes, int n_in,
                              void* d_out, int out_size) {
    const int*   tokens    = (const int*)  d_in[0];
    const int*   labels    = (const int*)  d_in[1];
    const float* emb       = (const float*)d_in[2];
    const float* in_proj_w = (const float*)d_in[3];
    const float* conv_w    = (const float*)d_in[4];
    const float* conv_b    = (const float*)d_in[5];
    const float* x_proj_w  = (const float*)d_in[6];
    const float* dt_proj_w = (const float*)d_in[7];
    const float* dt_proj_b = (const float*)d_in[8];
    const float* A_log     = (const float*)d_in[9];
    const float* Dp        = (const float*)d_in[10];
    const float* out_proj_w= (const float*)d_in[11];
    const float* norm_w    = (const float*)d_in[12];
    const float* norm_f_w  = (const float*)d_in[13];
    const float* topic_w   = (const float*)d_in[14];
    const float* topic_b   = (const float*)d_in[15];
    float* out = (float*)d_out;

    cudaFuncSetAttribute(mmgemm<0>, cudaFuncAttributeMaxDynamicSharedMemorySize, GEMM_SMEM);
    cudaFuncSetAttribute(mmgemm<2>, cudaFuncAttributeMaxDynamicSharedMemorySize, GEMM_SMEM);
    cudaFuncSetAttribute(mmgemm<3>, cudaFuncAttributeMaxDynamicSharedMemorySize, GEMM_SMEM);

    float *pH, *pXN, *pXZ, *pU, *pDBC, *pDELTA, *pY;
    cudaGetSymbolAddress((void**)&pH,     g_H);
    cudaGetSymbolAddress((void**)&pXN,    g_XN);
    cudaGetSymbolAddress((void**)&pXZ,    g_XZ);
    cudaGetSymbolAddress((void**)&pU,     g_U);
    cudaGetSymbolAddress((void**)&pDBC,   g_DBC);
    cudaGetSymbolAddress((void**)&pDELTA, g_DELTA);
    cudaGetSymbolAddress((void**)&pY,     g_Y);

    embed_kernel<<<(NROWS*DM + 255)/256, 256>>>(tokens, emb);

    for (int l = 0; l < NLAY; l++) {
        const float* ipw = in_proj_w + (size_t)l * 2*DI * DM;
        const float* cw  = conv_w    + (size_t)l * DI * DCV;
        const float* cb  = conv_b    + (size_t)l * DI;
        const float* xpw = x_proj_w  + (size_t)l * DXP * DI;
        const float* dpw = dt_proj_w + (size_t)l * DI * DR;
        const float* dpb = dt_proj_b + (size_t)l * DI;
        const float* Al  = A_log     + (size_t)l * DI * DS;
        const float* Dl  = Dp        + (size_t)l * DI;
        const float* opw = out_proj_w+ (size_t)l * DM * DI;
        const float* nw  = norm_w    + (size_t)l * DM;

        rmsnorm_kernel<<<NROWS, 256>>>(pH, nw, pXN);

        // XZ = XN @ in_proj^T  (4096 x 3072, K=768)
        {
            dim3 grid(2*DI/TN, NROWS/TM, 1);
            mmgemm<0><<<grid, 256, GEMM_SMEM>>>(pXN, ipw, pXZ, nullptr,
                                                2*DI, DM, DM, DM, DM);
        }

        conv_silu_kernel<<<(NROWS*DI + 255)/256, 256>>>(cw, cb);

        // DBC = U @ x_proj^T  (4096 x 80, K=1536)  split-K=4 atomic
        zero_kernel<<<(NROWS*DXP + 255)/256, 256>>>(pDBC, NROWS*DXP);
        {
            dim3 grid(1, NROWS/TM, 4);
            mmgemm<3><<<grid, 256, GEMM_SMEM>>>(pU, xpw, pDBC, nullptr,
                                                DXP, DI, DI, DI, DI/4);
        }

        // DELTA = softplus(DBC[:, :48] @ dt_proj^T + b)  (4096 x 1536, K=48)
        {
            dim3 grid(DI/TN, NROWS/TM, 1);
            mmgemm<2><<<grid, 256, GEMM_SMEM>>>(pDBC, dpw, pDELTA, dpb,
                                                DI, DR, DXP, DR, 64);
        }

        // chunked selective scan + gate -> Y
        scanA_kernel<<<(BB*DI*NCHK)/16, 256>>>(Al);
        scanB_kernel<<<(BB*DI*DS + 255)/256, 256>>>();
        scanC_kernel<<<(BB*DI*NCHK)/16, 256>>>(Al, Dl);

        // H += Y @ out_proj^T  (4096 x 768, K=1536)  split-K=2 atomic into residual
        {
            dim3 grid(DM/TN, NROWS/TM, 2);
            mmgemm<3><<<grid, 256, GEMM_SMEM>>>(pY, opw, pH, nullptr,
                                                DM, DI, DI, DI, DI/2);
        }
    }

    rmsnorm_kernel<<<NROWS, 256>>>(pH, norm_f_w, out + 7);
    topic_kernel<<<1, 192>>>(out + 7, topic_w, topic_b, out);
    loss_kernel<<<1, 1>>>(out, labels);
}